// round 12
// baseline (speedup 1.0000x reference)
#include <cuda_runtime.h>
#include <cuda_fp16.h>
#include <math.h>

#define NCH 256

// fp16 transposed [H,W,C] scratch for levels 3..5 (10.5 MB, L2-resident).
// Level 2 (~1.4% of boxes) is gathered directly from raw [C,H,W] fp32 p2.
__device__ __align__(16) __half g_t3[128 * 128 * NCH];  //  8 MB
__device__ __align__(16) __half g_t4[64 * 64 * NCH];    //  2 MB
__device__ __align__(16) __half g_t5[32 * 32 * NCH];    // 0.5 MB

#define NB3T 2048
#define NB4T 512
#define NB5T 128
#define NBT  (NB3T + NB4T + NB5T)

__global__ __launch_bounds__(256) void transpose345(
    const float* __restrict__ p3, const float* __restrict__ p4,
    const float* __restrict__ p5)
{
    __shared__ float tile[64][33];

    int bid = blockIdx.x;
    const float* __restrict__ in;
    __half* __restrict__ out;
    int HW;
    if (bid < NB3T)              { in = p3; out = g_t3; HW = 16384; }
    else if (bid < NB3T + NB4T)  { bid -= NB3T;        in = p4; out = g_t4; HW = 4096; }
    else                         { bid -= NB3T + NB4T; in = p5; out = g_t5; HW = 1024; }

    const int nhw = HW >> 5;
    const int hw0 = (bid % nhw) * 32;
    const int c0  = (bid / nhw) * 64;
    const int t = threadIdx.x;

    // Load: float4 per thread, 64 rows x 128B.
    const int r0 = t >> 3;          // 0..31
    const int c4 = (t & 7) * 4;     // 0,4,..,28
#pragma unroll
    for (int rr = 0; rr < 64; rr += 32) {
        const float4 v = *reinterpret_cast<const float4*>(
            &in[(size_t)(c0 + r0 + rr) * HW + hw0 + c4]);
        tile[r0 + rr][c4 + 0] = v.x;
        tile[r0 + rr][c4 + 1] = v.y;
        tile[r0 + rr][c4 + 2] = v.z;
        tile[r0 + rr][c4 + 3] = v.w;
    }
    __syncthreads();

    // Store: warp writes 32 half2 = 128B contiguous along C.
    const int tx = t & 31, ty = t >> 5;   // ty 0..7
#pragma unroll
    for (int hh = ty; hh < 32; hh += 8) {
        __half2 v = __floats2half2_rn(tile[2 * tx][hh], tile[2 * tx + 1][hh]);
        *reinterpret_cast<__half2*>(&out[(size_t)(hw0 + hh) * NCH + c0 + 2 * tx]) = v;
    }
}

// ONE 512-thread block per box (all 256 channels, all 49 samples).
// oe drops 8 -> 4 CTAs/SM at the same 64 warps/SM: per the B300 spread
// model (spr ~ oe * MLP_p1 cross-CTA L1tex-queue contention) this halves
// the contention term that kept three different gather shapes pinned at
// ~22.7us with no pipe above 52%. Geometry is computed once per box
// (was 4x). Warp-level access shape is unchanged from R9: 16 channel-quads
// per warp, LDG.64, one full 128B line per sample per LDG.
__global__ __launch_bounds__(512) void roi_gather(
    const float* __restrict__ boxes, const float* __restrict__ p2,
    float* __restrict__ out)
{
    __shared__ float  sm[NCH * 49];  // 50176 B staging, [c][s]
    __shared__ int4   offs[49];      // neighbor offsets (00,10,01,11)
    __shared__ float4 wts[49];       // fused weights  (w00,w10,w01,w11)

    const int b = blockIdx.x;

    const float y1 = boxes[4 * b + 0];
    const float x1 = boxes[4 * b + 1];
    const float y2 = boxes[4 * b + 2];
    const float x2 = boxes[4 * b + 3];
    const float h = y2 - y1;
    const float w = x2 - x1;

    const float lvl = 4.0f + log2f(sqrtf(h * w) / 0.21875f);
    int level = (int)rintf(lvl);
    level = min(5, max(2, level));

    const __half* __restrict__ fm16 = g_t5;
    int H = 32;
    if      (level == 2) { H = 256; }
    else if (level == 3) { fm16 = g_t3; H = 128; }
    else if (level == 4) { fm16 = g_t4; H = 64;  }
    const int W = H;
    const float Hm1 = (float)(H - 1);
    const int mul = (level == 2) ? 1 : NCH;   // offset units

    const int t = threadIdx.x;

    // ---- Phase 1: per-sample geometry (one thread per sample) ----
    if (t < 49) {
        const int py = t / 7;
        const int px = t - 7 * py;
        const float ys = (y1 + (float)py * (1.0f / 6.0f) * h) * Hm1;
        const float xs = (x1 + (float)px * (1.0f / 6.0f) * w) * Hm1;
        const float y0f = floorf(ys);
        const float x0f = floorf(xs);
        const float ly = ys - y0f;
        const float lx = xs - x0f;
        const int y0  = min(H - 1, max(0, (int)y0f));
        const int x0  = min(W - 1, max(0, (int)x0f));
        const int y1i = min(H - 1, y0 + 1);
        const int x1i = min(W - 1, x0 + 1);
        const float vv = ((ys >= 0.0f && ys <= Hm1) ? 1.0f : 0.0f) *
                         ((xs >= 0.0f && xs <= Hm1) ? 1.0f : 0.0f);
        const float wy0 = 1.0f - ly, wy1 = ly;
        const float wx0 = 1.0f - lx, wx1 = lx;
        offs[t] = make_int4((y0  * W + x0 ) * mul, (y1i * W + x0 ) * mul,
                            (y0  * W + x1i) * mul, (y1i * W + x1i) * mul);
        wts[t]  = make_float4(wy0 * wx0 * vv, wy1 * wx0 * vv,
                              wy0 * wx1 * vv, wy1 * wx1 * vv);
    }
    __syncthreads();

    // ---- Phase 2: gather. chunk q = t>>7 (64 channels), within chunk:
    //      quad p (channels 4p..4p+3), sample group sg (samples sg+8i). ----
    const int q     = t >> 7;            // 0..3
    const int local = t & 127;
    const int p     = local & 15;        // 16 quads
    const int sg    = local >> 4;        // 0..7
    const int c     = 64 * q + 4 * p;    // global channel base

    if (level != 2) {
        const __half* __restrict__ base = fm16 + c;
#pragma unroll
        for (int i = 0; i < 7; i++) {
            const int s = sg + 8 * i;
            if (s < 49) {
                const int4   o  = offs[s];
                const float4 wv = wts[s];
                const float2 v00 = *reinterpret_cast<const float2*>(base + o.x);
                const float2 v10 = *reinterpret_cast<const float2*>(base + o.y);
                const float2 v01 = *reinterpret_cast<const float2*>(base + o.z);
                const float2 v11 = *reinterpret_cast<const float2*>(base + o.w);
                const float2 a00 = __half22float2(*reinterpret_cast<const __half2*>(&v00.x));
                const float2 b00 = __half22float2(*reinterpret_cast<const __half2*>(&v00.y));
                const float2 a10 = __half22float2(*reinterpret_cast<const __half2*>(&v10.x));
                const float2 b10 = __half22float2(*reinterpret_cast<const __half2*>(&v10.y));
                const float2 a01 = __half22float2(*reinterpret_cast<const __half2*>(&v01.x));
                const float2 b01 = __half22float2(*reinterpret_cast<const __half2*>(&v01.y));
                const float2 a11 = __half22float2(*reinterpret_cast<const __half2*>(&v11.x));
                const float2 b11 = __half22float2(*reinterpret_cast<const __half2*>(&v11.y));
                sm[(c + 0) * 49 + s] =
                    a00.x * wv.x + a10.x * wv.y + a01.x * wv.z + a11.x * wv.w;
                sm[(c + 1) * 49 + s] =
                    a00.y * wv.x + a10.y * wv.y + a01.y * wv.z + a11.y * wv.w;
                sm[(c + 2) * 49 + s] =
                    b00.x * wv.x + b10.x * wv.y + b01.x * wv.z + b11.x * wv.w;
                sm[(c + 3) * 49 + s] =
                    b00.y * wv.x + b10.y * wv.y + b01.y * wv.z + b11.y * wv.w;
            }
        }
    } else {
        const float* __restrict__ bbase = p2 + (size_t)c * 65536;
#pragma unroll
        for (int i = 0; i < 7; i++) {
            const int s = sg + 8 * i;
            if (s < 49) {
                const int4   o  = offs[s];
                const float4 wv = wts[s];
#pragma unroll
                for (int j = 0; j < 4; j++) {
                    const float* __restrict__ bj = bbase + (size_t)j * 65536;
                    sm[(c + j) * 49 + s] =
                        bj[o.x] * wv.x + bj[o.y] * wv.y +
                        bj[o.z] * wv.z + bj[o.w] * wv.w;
                }
            }
        }
    }
    __syncthreads();

    // Box output is contiguous: 12544 floats = 3136 float4.
    const float4* __restrict__ sm4 = reinterpret_cast<const float4*>(sm);
    float4* __restrict__ ob = reinterpret_cast<float4*>(out + (size_t)b * (NCH * 49));
#pragma unroll
    for (int i = t; i < 3136; i += 512)
        ob[i] = sm4[i];
}

extern "C" void kernel_launch(void* const* d_in, const int* in_sizes, int n_in,
                              void* d_out, int out_size)
{
    const float* boxes = (const float*)d_in[0];
    const float* p2    = (const float*)d_in[1];
    const float* p3    = (const float*)d_in[2];
    const float* p4    = (const float*)d_in[3];
    const float* p5    = (const float*)d_in[4];
    float* out = (float*)d_out;

    transpose345<<<NBT, 256>>>(p3, p4, p5);

    const int nboxes = in_sizes[0] / 4;
    roi_gather<<<nboxes, 512>>>(boxes, p2, out);
}

// round 13
// speedup vs baseline: 2.7063x; 2.7063x over previous
#include <cuda_runtime.h>
#include <cuda_fp16.h>
#include <math.h>

#define NCH 256

// fp16 transposed [H,W,C] scratch for levels 3..5 (10.5 MB, L2-resident).
// Level 2 (~1.4% of boxes) is gathered directly from raw [C,H,W] fp32 p2.
__device__ __align__(16) __half g_t3[128 * 128 * NCH];  //  8 MB
__device__ __align__(16) __half g_t4[64 * 64 * NCH];    //  2 MB
__device__ __align__(16) __half g_t5[32 * 32 * NCH];    // 0.5 MB

#define NB3T 2048
#define NB4T 512
#define NB5T 128
#define NBT  (NB3T + NB4T + NB5T)

__global__ __launch_bounds__(256) void transpose345(
    const float* __restrict__ p3, const float* __restrict__ p4,
    const float* __restrict__ p5)
{
    __shared__ float tile[64][33];

    int bid = blockIdx.x;
    const float* __restrict__ in;
    __half* __restrict__ out;
    int HW;
    if (bid < NB3T)              { in = p3; out = g_t3; HW = 16384; }
    else if (bid < NB3T + NB4T)  { bid -= NB3T;        in = p4; out = g_t4; HW = 4096; }
    else                         { bid -= NB3T + NB4T; in = p5; out = g_t5; HW = 1024; }

    const int nhw = HW >> 5;
    const int hw0 = (bid % nhw) * 32;
    const int c0  = (bid / nhw) * 64;
    const int t = threadIdx.x;

    // Load: float4 per thread, 64 rows x 128B.
    const int r0 = t >> 3;          // 0..31
    const int c4 = (t & 7) * 4;     // 0,4,..,28
#pragma unroll
    for (int rr = 0; rr < 64; rr += 32) {
        const float4 v = *reinterpret_cast<const float4*>(
            &in[(size_t)(c0 + r0 + rr) * HW + hw0 + c4]);
        tile[r0 + rr][c4 + 0] = v.x;
        tile[r0 + rr][c4 + 1] = v.y;
        tile[r0 + rr][c4 + 2] = v.z;
        tile[r0 + rr][c4 + 3] = v.w;
    }
    __syncthreads();

    // Store: warp writes 32 half2 = 128B contiguous along C.
    const int tx = t & 31, ty = t >> 5;   // ty 0..7
#pragma unroll
    for (int hh = ty; hh < 32; hh += 8) {
        __half2 v = __floats2half2_rn(tile[2 * tx][hh], tile[2 * tx + 1][hh]);
        *reinterpret_cast<__half2*>(&out[(size_t)(hw0 + hh) * NCH + c0 + 2 * tx]) = v;
    }
}

// 4 blocks per box: blockIdx = box*4 + chunk (64 channels, all 49 samples).
// Phase 1: threads 0..48 precompute per-sample neighbor offsets + fused
// bilinear weights into smem.
// Phase 2: warp = 8 channel-OCTETS (p = t&7, LDG.128 = 8 halfs) x 4 samples.
// Per LDG.128: 8 threads x 16B = one full 128B line per sample-neighbor
// (100% line utilization, same wavefront count as R9) but HALF the LDG
// and address instructions, and 64B of payload in flight per iteration
// (2x R9's 32B). launch_bounds(256,4) gives the 64-reg budget R8 lacked
// (R8's LDG.128 at 32 regs collapsed MLP and regressed).
__global__ __launch_bounds__(256, 4) void roi_gather(
    const float* __restrict__ boxes, const float* __restrict__ p2,
    float* __restrict__ out)
{
    __shared__ float  sm[64 * 49];   // 12544 B staging, [c][s]
    __shared__ int4   offs[49];      // neighbor offsets (00,10,01,11)
    __shared__ float4 wts[49];       // fused weights  (w00,w10,w01,w11)

    const int b = blockIdx.x >> 2;
    const int q = blockIdx.x & 3;    // channel chunk: channels [64q, 64q+64)

    const float y1 = boxes[4 * b + 0];
    const float x1 = boxes[4 * b + 1];
    const float y2 = boxes[4 * b + 2];
    const float x2 = boxes[4 * b + 3];
    const float h = y2 - y1;
    const float w = x2 - x1;

    const float lvl = 4.0f + log2f(sqrtf(h * w) / 0.21875f);
    int level = (int)rintf(lvl);
    level = min(5, max(2, level));

    const __half* __restrict__ fm16 = g_t5;
    int H = 32;
    if      (level == 2) { H = 256; }
    else if (level == 3) { fm16 = g_t3; H = 128; }
    else if (level == 4) { fm16 = g_t4; H = 64;  }
    const int W = H;
    const float Hm1 = (float)(H - 1);
    const int mul = (level == 2) ? 1 : NCH;   // offset units

    const int t = threadIdx.x;

    // ---- Phase 1: per-sample geometry (one thread per sample) ----
    if (t < 49) {
        const int py = t / 7;
        const int px = t - 7 * py;
        const float ys = (y1 + (float)py * (1.0f / 6.0f) * h) * Hm1;
        const float xs = (x1 + (float)px * (1.0f / 6.0f) * w) * Hm1;
        const float y0f = floorf(ys);
        const float x0f = floorf(xs);
        const float ly = ys - y0f;
        const float lx = xs - x0f;
        const int y0  = min(H - 1, max(0, (int)y0f));
        const int x0  = min(W - 1, max(0, (int)x0f));
        const int y1i = min(H - 1, y0 + 1);
        const int x1i = min(W - 1, x0 + 1);
        const float vv = ((ys >= 0.0f && ys <= Hm1) ? 1.0f : 0.0f) *
                         ((xs >= 0.0f && xs <= Hm1) ? 1.0f : 0.0f);
        const float wy0 = 1.0f - ly, wy1 = ly;
        const float wx0 = 1.0f - lx, wx1 = lx;
        offs[t] = make_int4((y0  * W + x0 ) * mul, (y1i * W + x0 ) * mul,
                            (y0  * W + x1i) * mul, (y1i * W + x1i) * mul);
        wts[t]  = make_float4(wy0 * wx0 * vv, wy1 * wx0 * vv,
                              wy0 * wx1 * vv, wy1 * wx1 * vv);
    }
    __syncthreads();

    // ---- Phase 2: gather. octet p = t&7 (channels 8p..8p+7), sg = t>>3. ----
    const int p  = t & 7;
    const int sg = t >> 3;            // 0..31
    const int cl = 8 * p;             // local channel base within chunk

    if (level != 2) {
        const __half* __restrict__ base = fm16 + 64 * q + cl;
#pragma unroll
        for (int i = 0; i < 2; i++) {
            const int s = sg + 32 * i;
            if (s < 49) {
                const int4   o  = offs[s];
                const float4 wv = wts[s];
                const float4 v00 = *reinterpret_cast<const float4*>(base + o.x);
                const float4 v10 = *reinterpret_cast<const float4*>(base + o.y);
                const float4 v01 = *reinterpret_cast<const float4*>(base + o.z);
                const float4 v11 = *reinterpret_cast<const float4*>(base + o.w);
                const __half2* h00 = reinterpret_cast<const __half2*>(&v00);
                const __half2* h10 = reinterpret_cast<const __half2*>(&v10);
                const __half2* h01 = reinterpret_cast<const __half2*>(&v01);
                const __half2* h11 = reinterpret_cast<const __half2*>(&v11);
#pragma unroll
                for (int j = 0; j < 4; j++) {
                    const float2 f00 = __half22float2(h00[j]);
                    const float2 f10 = __half22float2(h10[j]);
                    const float2 f01 = __half22float2(h01[j]);
                    const float2 f11 = __half22float2(h11[j]);
                    sm[(cl + 2 * j)     * 49 + s] =
                        f00.x * wv.x + f10.x * wv.y + f01.x * wv.z + f11.x * wv.w;
                    sm[(cl + 2 * j + 1) * 49 + s] =
                        f00.y * wv.x + f10.y * wv.y + f01.y * wv.z + f11.y * wv.w;
                }
            }
        }
    } else {
        const float* __restrict__ bbase = p2 + (size_t)(64 * q + cl) * 65536;
#pragma unroll
        for (int i = 0; i < 2; i++) {
            const int s = sg + 32 * i;
            if (s < 49) {
                const int4   o  = offs[s];
                const float4 wv = wts[s];
#pragma unroll
                for (int j = 0; j < 8; j++) {
                    const float* __restrict__ bj = bbase + (size_t)j * 65536;
                    sm[(cl + j) * 49 + s] =
                        bj[o.x] * wv.x + bj[o.y] * wv.y +
                        bj[o.z] * wv.z + bj[o.w] * wv.w;
                }
            }
        }
    }
    __syncthreads();

    // Chunk output is contiguous: out[b][64q..64q+64][49] = 3136 floats.
    const float4* __restrict__ sm4 = reinterpret_cast<const float4*>(sm);
    float4* __restrict__ ob =
        reinterpret_cast<float4*>(out + (size_t)b * (NCH * 49) + (size_t)q * (64 * 49));
#pragma unroll
    for (int i = t; i < 784; i += 256)
        ob[i] = sm4[i];
}

extern "C" void kernel_launch(void* const* d_in, const int* in_sizes, int n_in,
                              void* d_out, int out_size)
{
    const float* boxes = (const float*)d_in[0];
    const float* p2    = (const float*)d_in[1];
    const float* p3    = (const float*)d_in[2];
    const float* p4    = (const float*)d_in[3];
    const float* p5    = (const float*)d_in[4];
    float* out = (float*)d_out;

    transpose345<<<NBT, 256>>>(p3, p4, p5);

    const int nboxes = in_sizes[0] / 4;
    roi_gather<<<4 * nboxes, 256>>>(boxes, p2, out);
}